// round 9
// baseline (speedup 1.0000x reference)
#include <cuda_runtime.h>
#include <cuda_fp16.h>

// gnn_42460046688469 — Fourier-graph gather + complex weighted aggregate + permuted scatter.
//
// R9 = R8 (fp16 L2-resident scratch, 223.5us) restructured to TWO launches:
//   [repack, main]  (detect kernel removed)
// Config detection (operand order / index width / size units) now runs as a
// redundant per-block prologue in BOTH kernels: every block performs the same
// 256 probe loads (block 0 from DRAM, all others L2 hits) and reduces in
// shared memory. Deterministic, ~<2us total. This also puts the main kernel
// back at ncu's -s 5 skip position (it was profiling detect since R6).
// Because repack no longer learns imagFirst from a prior kernel, the scratch
// stores (xf0,xf1) pairs in PRESENTED order and the main kernel swaps
// real/imag lanes at read time (register selects on the idle fma/alu pipes).
//
// Core (proven R6-R8): per-launch repack of Xf into an interleaved fp16
// complex table (64 B/row, 67 MB -> L2-resident); gathers touch exactly one
// fully-used line. All gathered indices clamped; output layout chosen from
// out_size; all stores bounded.

#define K_NB 8

struct Cfg { int u; int is64; int niSel; int imagFirst; };

// Interleaved fp16 table, PRESENTED order (xf0,xf1): 1,048,576 rows x 64 B.
__device__ __align__(16) uint4 g_scratch[4194304];

// Per-block config detection. Must be called by all 256 threads of a block.
// Probe positions identical to the R7/R8 detect kernel (proven decisions).
__device__ __forceinline__ Cfg block_detect_cfg(
    const unsigned* __restrict__ m0, const unsigned* __restrict__ m1,
    const unsigned* __restrict__ m2, const unsigned* __restrict__ hind,
    int s_mid, int s_hi)
{
    __shared__ int sOk[3];
    __shared__ int sZeros;
    __shared__ unsigned sVmax;
    __shared__ int sIs64;
    __shared__ Cfg sCfg;

    int tid = threadIdx.x;
    if (tid < 3) sOk[tid] = 1;
    if (tid == 3) sZeros = 0;
    if (tid == 4) sVmax = 0u;
    __syncthreads();

    int Wm = s_mid >> 2;   // words provably in-bounds under both unit schemes
    int Wh = s_hi >> 2;

    if (tid < 192) {
        int b = tid >> 6;
        int j = tid & 63;
        int step = Wm / 67; if (step < 1) step = 1;
        const unsigned* ms = (b == 0) ? m0 : (b == 1) ? m1 : m2;
        unsigned v = __ldg(ms + (j * step + j) % Wm);
        if (v >= 0x01000000u) atomicExch(&sOk[b], 0);
    } else if (tid < 256) {
        int j = tid - 192;
        int step = Wh / 67; if (step < 1) step = 1;
        int w = ((j * step + j) % Wh) | 1;
        if (__ldg(hind + w) == 0u) atomicAdd(&sZeros, 1);
    }
    __syncthreads();
    if (tid == 0) sIs64 = (sZeros >= 48) ? 1 : 0;
    __syncthreads();

    if (tid >= 192 && tid < 256) {
        int j = tid - 192;
        int step = Wh / 67; if (step < 1) step = 1;
        int w = (j * step + j) % Wh;
        if (sIs64) w &= ~1;
        atomicMax(&sVmax, __ldg(hind + w));
    }
    __syncthreads();

    if (tid == 0) {
        int niSel = 2;
        if (sOk[0] && !sOk[2]) niSel = 0;
        else if (sOk[1] && !sOk[0] && !sOk[2]) niSel = 1;
        int imagFirst = (niSel == 0) ? 1 : 0;
        unsigned thresh = sIs64 ? (unsigned)(s_hi >> 3) : (unsigned)(s_hi >> 2);
        int u = (sVmax >= thresh) ? 1 : 4;
        Cfg c; c.u = u; c.is64 = sIs64; c.niSel = niSel; c.imagFirst = imagFirst;
        sCfg = c;
    }
    __syncthreads();
    return sCfg;
}

// Streaming repack: split fp32 xf0/xf1 -> interleaved __half2 (xf0,xf1) rows.
// Thread i handles 4 channels of one row. Order-agnostic (no imagFirst).
__global__ void __launch_bounds__(256) repack_kernel(
    const float* __restrict__ xf0, const float* __restrict__ xf1,
    const unsigned* __restrict__ m0, const unsigned* __restrict__ m1,
    const unsigned* __restrict__ m2, const unsigned* __restrict__ hind,
    int s_max, int s_mid, int s_hi)
{
    Cfg c = block_detect_cfg(m0, m1, m2, hind, s_mid, s_hi);
    int Mrows = (s_max / c.u) / 16;
    int i = blockIdx.x * blockDim.x + threadIdx.x;
    if (i >= Mrows * 4) return;

    float4 xa = __ldg((const float4*)xf0 + i);
    float4 xb = __ldg((const float4*)xf1 + i);

    __half2 h0 = __floats2half2_rn(xa.x, xb.x);
    __half2 h1 = __floats2half2_rn(xa.y, xb.y);
    __half2 h2 = __floats2half2_rn(xa.z, xb.z);
    __half2 h3 = __floats2half2_rn(xa.w, xb.w);

    uint4 o;
    o.x = *reinterpret_cast<unsigned*>(&h0);
    o.y = *reinterpret_cast<unsigned*>(&h1);
    o.z = *reinterpret_cast<unsigned*>(&h2);
    o.w = *reinterpret_cast<unsigned*>(&h3);
    g_scratch[i] = o;
}

__device__ __forceinline__ int load_idx(const void* p, int off, int is64) {
    return is64 ? (int)((const long long*)p)[off] : ((const int*)p)[off];
}

__device__ __forceinline__ float2 h2f(unsigned u) {
    __half2 h = *reinterpret_cast<__half2*>(&u);
    return __half22float2(h);
}

__global__ void __launch_bounds__(256, 8) gnn_fourier_kernel(
    const void*  __restrict__ m0,  const void*  __restrict__ m1,
    const void*  __restrict__ m2,
    const void*  __restrict__ hmask, const void* __restrict__ hind,
    float4* __restrict__ out,
    int s_max, int s_mid, int s_hi, int s_hm, int out_count)
{
    Cfg c = block_detect_cfg((const unsigned*)m0, (const unsigned*)m1,
                             (const unsigned*)m2, (const unsigned*)hind,
                             s_mid, s_hi);

    int idxDiv = c.u * ((c.is64 && c.u == 4) ? 2 : 1);
    int NH     = s_hi / idxDiv;
    int H      = s_hm / idxDiv;
    int N      = (s_mid / c.u) / K_NB;
    int Mrows  = (s_max / c.u) / 16;

    int gid = blockIdx.x * blockDim.x + threadIdx.x;
    int row = gid >> 2;
    if (row >= NH) return;
    int t = gid & 3;

    const void* mids[3] = { m0, m1, m2 };
    const void* NIp = mids[c.niSel];
    const void* wa  = (c.niSel == 0) ? m1 : m0;
    const void* wb  = (c.niSel == 2) ? m1 : m2;
    const float* wR = (const float*)(c.imagFirst ? wb : wa);
    const float* wI = (const float*)(c.imagFirst ? wa : wb);
    // scratch lanes: (xf0,xf1) = imagFirst ? (im,re) : (re,im)
    int swap = c.imagFirst;

    unsigned src = (unsigned)load_idx(hind, row, c.is64);
    src = min(src, (unsigned)(NH - 1));

    const uint4* S = g_scratch;
    float4 a0, a1;   // interleaved (re,im) accumulators: channels [4t, 4t+4)

    if ((int)src < N) {
        a0 = make_float4(0.f, 0.f, 0.f, 0.f);
        a1 = make_float4(0.f, 0.f, 0.f, 0.f);
        #pragma unroll
        for (int k = 0; k < K_NB; ++k) {
            int off = k * N + (int)src;
            unsigned idx = (unsigned)load_idx(NIp, off, c.is64);
            idx = min(idx, (unsigned)(Mrows - 1));
            float wr = __ldg(wR + off);
            float wi = __ldg(wI + off);
            uint4 v = __ldg(S + (long long)idx * 4 + t);
            float2 p0 = h2f(v.x), p1 = h2f(v.y), p2 = h2f(v.z), p3 = h2f(v.w);
            float r0 = swap ? p0.y : p0.x, i0 = swap ? p0.x : p0.y;
            float r1 = swap ? p1.y : p1.x, i1 = swap ? p1.x : p1.y;
            float r2 = swap ? p2.y : p2.x, i2 = swap ? p2.x : p2.y;
            float r3 = swap ? p3.y : p3.x, i3 = swap ? p3.x : p3.y;
            a0.x = fmaf(wr, r0, fmaf(-wi, i0, a0.x));
            a0.y = fmaf(wr, i0, fmaf( wi, r0, a0.y));
            a0.z = fmaf(wr, r1, fmaf(-wi, i1, a0.z));
            a0.w = fmaf(wr, i1, fmaf( wi, r1, a0.w));
            a1.x = fmaf(wr, r2, fmaf(-wi, i2, a1.x));
            a1.y = fmaf(wr, i2, fmaf( wi, r2, a1.y));
            a1.z = fmaf(wr, r3, fmaf(-wi, i3, a1.z));
            a1.w = fmaf(wr, i3, fmaf( wi, r3, a1.w));
        }
    } else {
        unsigned hoff = min((unsigned)((int)src - N), (unsigned)(H - 1));
        unsigned idx = (unsigned)load_idx(hmask, (int)hoff, c.is64);
        idx = min(idx, (unsigned)(Mrows - 1));
        uint4 v = __ldg(S + (long long)idx * 4 + t);
        float2 p0 = h2f(v.x), p1 = h2f(v.y), p2 = h2f(v.z), p3 = h2f(v.w);
        if (swap) {
            a0 = make_float4(p0.y, p0.x, p1.y, p1.x);
            a1 = make_float4(p2.y, p2.x, p3.y, p3.x);
        } else {
            a0 = make_float4(p0.x, p0.y, p1.x, p1.y);
            a1 = make_float4(p2.x, p2.y, p3.x, p3.y);
        }
    }

    long long needF = (long long)NH * 32;
    int maxF4 = out_count >> 2;

    if ((long long)out_count >= needF) {
        int ob = row * 8 + t * 2;
        if (ob + 1 < maxF4) {
            out[ob]     = a0;
            out[ob + 1] = a1;
        }
    } else {
        int ob = row * 4 + t;
        if (ob < maxF4) out[ob] = make_float4(a0.x, a0.z, a1.x, a1.z);
    }
}

extern "C" void kernel_launch(void* const* d_in, const int* in_sizes, int n_in,
                              void* d_out, int out_size) {
    int smax = 0;
    for (int i = 0; i < n_in; ++i) if (in_sizes[i] > smax) smax = in_sizes[i];

    int smid = 0;
    for (int i = 0; i < n_in && !smid; ++i) {
        int s = in_sizes[i];
        if (s == smax || s <= 64) continue;
        int cnt = 0;
        for (int j = 0; j < n_in; ++j) if (in_sizes[j] == s) cnt++;
        if (cnt == 3) smid = s;
    }

    const float* xf[2] = { 0, 0 }; int nx = 0;
    const void*  mid[3] = { 0, 0, 0 }; int nm = 0;
    int hiPos = -1, hmPos = -1;
    if (smid) {
        for (int i = 0; i < n_in; ++i) {
            int s = in_sizes[i];
            if (s == smax)      { if (nx < 2) xf[nx++] = (const float*)d_in[i]; }
            else if (s == smid) { if (nm < 3) mid[nm++] = d_in[i]; }
            else if (s > 64) {
                if (hiPos < 0) hiPos = i;
                else if (s > in_sizes[hiPos]) { hmPos = hiPos; hiPos = i; }
                else hmPos = i;
            }
        }
    } else {
        int s2 = 0;
        for (int i = 0; i < n_in && !s2; ++i) {
            int s = in_sizes[i];
            if (s == smax || s <= 64) continue;
            int cnt = 0;
            for (int j = 0; j < n_in; ++j) if (in_sizes[j] == s) cnt++;
            if (cnt == 2) s2 = s;
        }
        smid = s2;
        int niPos = -1;
        for (int i = 0; i < n_in; ++i) if (in_sizes[i] == 2 * s2) niPos = i;
        int order[3], no = 0;
        for (int i = 0; i < n_in && no < 3; ++i)
            if (in_sizes[i] == s2 || i == niPos) order[no++] = i;
        for (int q = 0; q < 3; ++q) mid[q] = d_in[order[q]];
        for (int i = 0; i < n_in; ++i) {
            int s = in_sizes[i];
            if (s == smax) { if (nx < 2) xf[nx++] = (const float*)d_in[i]; }
            else if (s > 64 && s != s2 && i != niPos) {
                if (hiPos < 0) hiPos = i;
                else if (s > in_sizes[hiPos]) { hmPos = hiPos; hiPos = i; }
                else hmPos = i;
            }
        }
    }

    int s_hi = in_sizes[hiPos];
    int s_hm = in_sizes[hmPos];

    {
        long long rthreads = (long long)smax / 4;
        int block = 256;
        long long rgrid = (rthreads + block - 1) / block;
        repack_kernel<<<(int)rgrid, block>>>(xf[0], xf[1],
                                             (const unsigned*)mid[0],
                                             (const unsigned*)mid[1],
                                             (const unsigned*)mid[2],
                                             (const unsigned*)d_in[hiPos],
                                             smax, smid, s_hi);
    }

    long long rows_max = s_hi;   // worst case; excess threads exit
    long long total_threads = rows_max * 4;
    int block = 256;
    long long grid = (total_threads + block - 1) / block;

    gnn_fourier_kernel<<<(int)grid, block>>>(mid[0], mid[1], mid[2],
                                             d_in[hmPos], d_in[hiPos],
                                             (float4*)d_out,
                                             smax, smid, s_hi, s_hm, out_size);
}

// round 10
// speedup vs baseline: 1.2463x; 1.2463x over previous
#include <cuda_runtime.h>
#include <cuda_fp16.h>

// gnn_42460046688469 — Fourier-graph gather + complex weighted aggregate + permuted scatter.
//
// R10 = R8 (223.5us best: 3 launches, fp16 interleaved scratch) + streaming
// cache hints on the use-once streams. R9's main-kernel profile showed
// ~856 MB DRAM/launch vs ~190 MB compulsory: ~600 MB is gather misses from
// the 67 MB fp16 table being evicted by the ~190 MB of streams. Unlike R5
// (fp32 table 134 MB > L2 -> hints could not matter), the table now fits L2
// with room to spare, so evict-first streams (__ldcs/__stcs) + normal-policy
// gathers should keep it resident. R9's inlined-detect + lane-swap is
// reverted (measured +58us on the main kernel).
//
// Interface handling (proven R4-R8): content-based detection of operand
// order / index width / size units; every gathered index clamped; output
// layout chosen from out_size; all stores bounded.

#define K_NB 8

struct Cfg { int u; int is64; int niSel; int imagFirst; };
__device__ Cfg g_cfg;

// Interleaved fp16 complex table: up to 1,048,576 rows x 64 B (67 MB).
__device__ __align__(16) uint4 g_scratch[4194304];

__global__ void detect_kernel(const unsigned* __restrict__ m0,
                              const unsigned* __restrict__ m1,
                              const unsigned* __restrict__ m2,
                              const unsigned* __restrict__ hind,
                              int s_mid, int s_hi)
{
    __shared__ int sOk[3];
    __shared__ int sZeros;
    __shared__ unsigned sVmax;
    __shared__ int sIs64;

    int tid = threadIdx.x;
    if (tid < 3) sOk[tid] = 1;
    if (tid == 3) sZeros = 0;
    if (tid == 4) sVmax = 0u;
    __syncthreads();

    int Wm = s_mid >> 2;   // words provably in-bounds under both unit schemes
    int Wh = s_hi >> 2;

    if (tid < 192) {
        int b = tid >> 6;
        int j = tid & 63;
        int step = Wm / 67; if (step < 1) step = 1;
        const unsigned* ms = (b == 0) ? m0 : (b == 1) ? m1 : m2;
        unsigned v = ms[(j * step + j) % Wm];
        if (v >= 0x01000000u) atomicExch(&sOk[b], 0);
    } else {
        int j = tid - 192;
        int step = Wh / 67; if (step < 1) step = 1;
        int w = ((j * step + j) % Wh) | 1;
        if (hind[w] == 0u) atomicAdd(&sZeros, 1);
    }
    __syncthreads();
    if (tid == 0) sIs64 = (sZeros >= 48) ? 1 : 0;
    __syncthreads();

    if (tid >= 192) {
        int j = tid - 192;
        int step = Wh / 67; if (step < 1) step = 1;
        int w = (j * step + j) % Wh;
        if (sIs64) w &= ~1;
        atomicMax(&sVmax, hind[w]);
    }
    __syncthreads();

    if (tid == 0) {
        int niSel = 2;
        if (sOk[0] && !sOk[2]) niSel = 0;
        else if (sOk[1] && !sOk[0] && !sOk[2]) niSel = 1;
        int imagFirst = (niSel == 0) ? 1 : 0;

        unsigned thresh = sIs64 ? (unsigned)(s_hi >> 3) : (unsigned)(s_hi >> 2);
        int u = (sVmax >= thresh) ? 1 : 4;

        Cfg c; c.u = u; c.is64 = sIs64; c.niSel = niSel; c.imagFirst = imagFirst;
        g_cfg = c;
    }
}

// Streaming repack: split fp32 Xf_real/Xf_imag -> interleaved __half2 rows.
// Reads are use-once (__ldcs); scratch stores use default policy (the table
// should be L2-welcome — it is about to be gathered from heavily).
__global__ void __launch_bounds__(256) repack_kernel(
    const float* __restrict__ xf0, const float* __restrict__ xf1, int s_max)
{
    Cfg c = g_cfg;
    int Mrows = (s_max / c.u) / 16;
    int i = blockIdx.x * blockDim.x + threadIdx.x;
    if (i >= Mrows * 4) return;

    const float4* R = (const float4*)(c.imagFirst ? xf1 : xf0);
    const float4* I = (const float4*)(c.imagFirst ? xf0 : xf1);
    float4 xr = __ldcs(R + i);
    float4 xi = __ldcs(I + i);

    __half2 h0 = __floats2half2_rn(xr.x, xi.x);
    __half2 h1 = __floats2half2_rn(xr.y, xi.y);
    __half2 h2 = __floats2half2_rn(xr.z, xi.z);
    __half2 h3 = __floats2half2_rn(xr.w, xi.w);

    uint4 o;
    o.x = *reinterpret_cast<unsigned*>(&h0);
    o.y = *reinterpret_cast<unsigned*>(&h1);
    o.z = *reinterpret_cast<unsigned*>(&h2);
    o.w = *reinterpret_cast<unsigned*>(&h3);
    g_scratch[i] = o;
}

// streaming (evict-first) index load
__device__ __forceinline__ int load_idx_cs(const void* p, int off, int is64) {
    return is64 ? (int)__ldcs((const long long*)p + off)
                : __ldcs((const int*)p + off);
}

__device__ __forceinline__ float2 h2f(unsigned u) {
    __half2 h = *reinterpret_cast<__half2*>(&u);
    return __half22float2(h);
}

__global__ void __launch_bounds__(256, 8) gnn_fourier_kernel(
    const void*  __restrict__ m0,  const void*  __restrict__ m1,
    const void*  __restrict__ m2,
    const void*  __restrict__ hmask, const void* __restrict__ hind,
    float4* __restrict__ out,
    int s_max, int s_mid, int s_hi, int s_hm, int out_count)
{
    Cfg c = g_cfg;

    int idxDiv = c.u * ((c.is64 && c.u == 4) ? 2 : 1);
    int NH     = s_hi / idxDiv;
    int H      = s_hm / idxDiv;
    int N      = (s_mid / c.u) / K_NB;
    int Mrows  = (s_max / c.u) / 16;

    int gid = blockIdx.x * blockDim.x + threadIdx.x;
    int row = gid >> 2;
    if (row >= NH) return;
    int t = gid & 3;

    const void* mids[3] = { m0, m1, m2 };
    const void* NIp = mids[c.niSel];
    const void* wa  = (c.niSel == 0) ? m1 : m0;
    const void* wb  = (c.niSel == 2) ? m1 : m2;
    const float* wR = (const float*)(c.imagFirst ? wb : wa);
    const float* wI = (const float*)(c.imagFirst ? wa : wb);

    unsigned src = (unsigned)load_idx_cs(hind, row, c.is64);
    src = min(src, (unsigned)(NH - 1));

    const uint4* S = g_scratch;
    float4 a0, a1;   // interleaved (re,im) accumulators: channels [4t, 4t+4)

    if ((int)src < N) {
        a0 = make_float4(0.f, 0.f, 0.f, 0.f);
        a1 = make_float4(0.f, 0.f, 0.f, 0.f);
        #pragma unroll
        for (int k = 0; k < K_NB; ++k) {
            int off = k * N + (int)src;
            unsigned idx = (unsigned)load_idx_cs(NIp, off, c.is64);
            idx = min(idx, (unsigned)(Mrows - 1));
            float wr = __ldcs(wR + off);
            float wi = __ldcs(wI + off);
            // table gather: DEFAULT policy -> stays resident in L2
            uint4 v = __ldg(S + (long long)idx * 4 + t);
            float2 f0 = h2f(v.x), f1 = h2f(v.y), f2 = h2f(v.z), f3 = h2f(v.w);
            a0.x = fmaf(wr, f0.x, fmaf(-wi, f0.y, a0.x));
            a0.y = fmaf(wr, f0.y, fmaf( wi, f0.x, a0.y));
            a0.z = fmaf(wr, f1.x, fmaf(-wi, f1.y, a0.z));
            a0.w = fmaf(wr, f1.y, fmaf( wi, f1.x, a0.w));
            a1.x = fmaf(wr, f2.x, fmaf(-wi, f2.y, a1.x));
            a1.y = fmaf(wr, f2.y, fmaf( wi, f2.x, a1.y));
            a1.z = fmaf(wr, f3.x, fmaf(-wi, f3.y, a1.z));
            a1.w = fmaf(wr, f3.y, fmaf( wi, f3.x, a1.w));
        }
    } else {
        unsigned hoff = min((unsigned)((int)src - N), (unsigned)(H - 1));
        unsigned idx = (unsigned)load_idx_cs(hmask, (int)hoff, c.is64);
        idx = min(idx, (unsigned)(Mrows - 1));
        uint4 v = __ldg(S + (long long)idx * 4 + t);
        float2 f0 = h2f(v.x), f1 = h2f(v.y), f2 = h2f(v.z), f3 = h2f(v.w);
        a0 = make_float4(f0.x, f0.y, f1.x, f1.y);
        a1 = make_float4(f2.x, f2.y, f3.x, f3.y);
    }

    long long needF = (long long)NH * 32;
    int maxF4 = out_count >> 2;

    if ((long long)out_count >= needF) {
        int ob = row * 8 + t * 2;
        if (ob + 1 < maxF4) {
            __stcs(out + ob,     a0);
            __stcs(out + ob + 1, a1);
        }
    } else {
        int ob = row * 4 + t;
        if (ob < maxF4) __stcs(out + ob, make_float4(a0.x, a0.z, a1.x, a1.z));
    }
}

extern "C" void kernel_launch(void* const* d_in, const int* in_sizes, int n_in,
                              void* d_out, int out_size) {
    int smax = 0;
    for (int i = 0; i < n_in; ++i) if (in_sizes[i] > smax) smax = in_sizes[i];

    int smid = 0;
    for (int i = 0; i < n_in && !smid; ++i) {
        int s = in_sizes[i];
        if (s == smax || s <= 64) continue;
        int cnt = 0;
        for (int j = 0; j < n_in; ++j) if (in_sizes[j] == s) cnt++;
        if (cnt == 3) smid = s;
    }

    const float* xf[2] = { 0, 0 }; int nx = 0;
    const void*  mid[3] = { 0, 0, 0 }; int nm = 0;
    int hiPos = -1, hmPos = -1;
    if (smid) {
        for (int i = 0; i < n_in; ++i) {
            int s = in_sizes[i];
            if (s == smax)      { if (nx < 2) xf[nx++] = (const float*)d_in[i]; }
            else if (s == smid) { if (nm < 3) mid[nm++] = d_in[i]; }
            else if (s > 64) {
                if (hiPos < 0) hiPos = i;
                else if (s > in_sizes[hiPos]) { hmPos = hiPos; hiPos = i; }
                else hmPos = i;
            }
        }
    } else {
        int s2 = 0;
        for (int i = 0; i < n_in && !s2; ++i) {
            int s = in_sizes[i];
            if (s == smax || s <= 64) continue;
            int cnt = 0;
            for (int j = 0; j < n_in; ++j) if (in_sizes[j] == s) cnt++;
            if (cnt == 2) s2 = s;
        }
        smid = s2;
        int niPos = -1;
        for (int i = 0; i < n_in; ++i) if (in_sizes[i] == 2 * s2) niPos = i;
        int order[3], no = 0;
        for (int i = 0; i < n_in && no < 3; ++i)
            if (in_sizes[i] == s2 || i == niPos) order[no++] = i;
        for (int q = 0; q < 3; ++q) mid[q] = d_in[order[q]];
        for (int i = 0; i < n_in; ++i) {
            int s = in_sizes[i];
            if (s == smax) { if (nx < 2) xf[nx++] = (const float*)d_in[i]; }
            else if (s > 64 && s != s2 && i != niPos) {
                if (hiPos < 0) hiPos = i;
                else if (s > in_sizes[hiPos]) { hmPos = hiPos; hiPos = i; }
                else hmPos = i;
            }
        }
    }

    int s_hi = in_sizes[hiPos];
    int s_hm = in_sizes[hmPos];

    detect_kernel<<<1, 256>>>((const unsigned*)mid[0], (const unsigned*)mid[1],
                              (const unsigned*)mid[2], (const unsigned*)d_in[hiPos],
                              smid, s_hi);

    {
        long long rthreads = (long long)smax / 4;
        int block = 256;
        long long rgrid = (rthreads + block - 1) / block;
        repack_kernel<<<(int)rgrid, block>>>(xf[0], xf[1], smax);
    }

    long long rows_max = s_hi;   // worst case; excess threads exit
    long long total_threads = rows_max * 4;
    int block = 256;
    long long grid = (total_threads + block - 1) / block;

    gnn_fourier_kernel<<<(int)grid, block>>>(mid[0], mid[1], mid[2],
                                             d_in[hmPos], d_in[hiPos],
                                             (float4*)d_out,
                                             smax, smid, s_hi, s_hm, out_size);
}

// round 11
// speedup vs baseline: 1.8432x; 1.4790x over previous
#include <cuda_runtime.h>
#include <cuda_fp16.h>

// gnn_42460046688469 — Fourier-graph gather + complex weighted aggregate + permuted scatter.
//
// R11 = R8 core (223.5us best) + PACKED PER-NODE WEIGHT RECORDS.
// The NI/w loads are themselves random gathers (indexed by permuted src):
// 24 scattered 4B touches per row = 768B of sector traffic and ~24 L1
// wavefronts per row for 96 useful bytes — about half the kernel's L1 work,
// spent on metadata. A third prologue kernel (repack2) transposes
// (NI, w_real, w_imag) into one 128B-padded record per node:
//     [idx[8] (clamped) | wr[8] | wi[8] | pad]   (67 MB scratch)
// so the main kernel's quad reads its entire weight set as 6 broadcast
// LDG.128 from a single line. fp16 table gathers / math / output unchanged
// (rel_err must remain 2.078e-4). R10 cache hints reverted (2x measured
// neutral).
//
// Launches: detect (5us) -> repack Xf (fp16 table) -> repack2 (NI/w) -> main.
//
// Interface handling (proven R4-R10): content-based detection of operand
// order / index width / size units; every gathered index clamped; output
// layout chosen from out_size; all stores bounded.

#define K_NB 8

struct Cfg { int u; int is64; int niSel; int imagFirst; };
__device__ Cfg g_cfg;

// Interleaved fp16 complex table: up to 1,048,576 rows x 64 B (67 MB).
__device__ __align__(16) uint4 g_scratch[4194304];
// Packed per-node records: up to 524,288 nodes x 128 B (67 MB).
__device__ __align__(16) uint4 g_pack[4194304];

__global__ void detect_kernel(const unsigned* __restrict__ m0,
                              const unsigned* __restrict__ m1,
                              const unsigned* __restrict__ m2,
                              const unsigned* __restrict__ hind,
                              int s_mid, int s_hi)
{
    __shared__ int sOk[3];
    __shared__ int sZeros;
    __shared__ unsigned sVmax;
    __shared__ int sIs64;

    int tid = threadIdx.x;
    if (tid < 3) sOk[tid] = 1;
    if (tid == 3) sZeros = 0;
    if (tid == 4) sVmax = 0u;
    __syncthreads();

    int Wm = s_mid >> 2;   // words provably in-bounds under both unit schemes
    int Wh = s_hi >> 2;

    if (tid < 192) {
        int b = tid >> 6;
        int j = tid & 63;
        int step = Wm / 67; if (step < 1) step = 1;
        const unsigned* ms = (b == 0) ? m0 : (b == 1) ? m1 : m2;
        unsigned v = ms[(j * step + j) % Wm];
        if (v >= 0x01000000u) atomicExch(&sOk[b], 0);
    } else {
        int j = tid - 192;
        int step = Wh / 67; if (step < 1) step = 1;
        int w = ((j * step + j) % Wh) | 1;
        if (hind[w] == 0u) atomicAdd(&sZeros, 1);
    }
    __syncthreads();
    if (tid == 0) sIs64 = (sZeros >= 48) ? 1 : 0;
    __syncthreads();

    if (tid >= 192) {
        int j = tid - 192;
        int step = Wh / 67; if (step < 1) step = 1;
        int w = (j * step + j) % Wh;
        if (sIs64) w &= ~1;
        atomicMax(&sVmax, hind[w]);
    }
    __syncthreads();

    if (tid == 0) {
        int niSel = 2;
        if (sOk[0] && !sOk[2]) niSel = 0;
        else if (sOk[1] && !sOk[0] && !sOk[2]) niSel = 1;
        int imagFirst = (niSel == 0) ? 1 : 0;

        unsigned thresh = sIs64 ? (unsigned)(s_hi >> 3) : (unsigned)(s_hi >> 2);
        int u = (sVmax >= thresh) ? 1 : 4;

        Cfg c; c.u = u; c.is64 = sIs64; c.niSel = niSel; c.imagFirst = imagFirst;
        g_cfg = c;
    }
}

// Streaming repack: split fp32 Xf_real/Xf_imag -> interleaved __half2 rows.
__global__ void __launch_bounds__(256) repack_kernel(
    const float* __restrict__ xf0, const float* __restrict__ xf1, int s_max)
{
    Cfg c = g_cfg;
    int Mrows = (s_max / c.u) / 16;
    int i = blockIdx.x * blockDim.x + threadIdx.x;
    if (i >= Mrows * 4) return;

    const float4* R = (const float4*)(c.imagFirst ? xf1 : xf0);
    const float4* I = (const float4*)(c.imagFirst ? xf0 : xf1);
    float4 xr = __ldg(R + i);
    float4 xi = __ldg(I + i);

    __half2 h0 = __floats2half2_rn(xr.x, xi.x);
    __half2 h1 = __floats2half2_rn(xr.y, xi.y);
    __half2 h2 = __floats2half2_rn(xr.z, xi.z);
    __half2 h3 = __floats2half2_rn(xr.w, xi.w);

    uint4 o;
    o.x = *reinterpret_cast<unsigned*>(&h0);
    o.y = *reinterpret_cast<unsigned*>(&h1);
    o.z = *reinterpret_cast<unsigned*>(&h2);
    o.w = *reinterpret_cast<unsigned*>(&h3);
    g_scratch[i] = o;
}

__device__ __forceinline__ int load_idx(const void* p, int off, int is64) {
    return is64 ? (int)((const long long*)p)[off] : ((const int*)p)[off];
}

// Transpose (NI, w_real, w_imag) from (K,N) into per-node 128B records:
//   uint4[8]: [idx0-3][idx4-7][wr0-3][wr4-7][wi0-3][wi4-7][pad][pad]
// Reads are coalesced along n; idx is clamped here so the main kernel
// needs no per-gather min().
__global__ void __launch_bounds__(256) repack2_kernel(
    const void* __restrict__ m0, const void* __restrict__ m1,
    const void* __restrict__ m2, int s_mid, int s_max)
{
    Cfg c = g_cfg;
    int N     = (s_mid / c.u) / K_NB;
    int Mrows = (s_max / c.u) / 16;
    int n = blockIdx.x * blockDim.x + threadIdx.x;
    if (n >= N) return;

    const void* mids[3] = { m0, m1, m2 };
    const void* NIp = mids[c.niSel];
    const void* wa  = (c.niSel == 0) ? m1 : m0;
    const void* wb  = (c.niSel == 2) ? m1 : m2;
    const float* wR = (const float*)(c.imagFirst ? wb : wa);
    const float* wI = (const float*)(c.imagFirst ? wa : wb);

    unsigned idxA[8]; unsigned wrA[8]; unsigned wiA[8];
    #pragma unroll
    for (int k = 0; k < K_NB; ++k) {
        int off = k * N + n;
        unsigned idx = (unsigned)load_idx(NIp, off, c.is64);
        idxA[k] = min(idx, (unsigned)(Mrows - 1));
        wrA[k]  = __float_as_uint(__ldg(wR + off));
        wiA[k]  = __float_as_uint(__ldg(wI + off));
    }

    uint4* P = g_pack + (size_t)n * 8;
    P[0] = make_uint4(idxA[0], idxA[1], idxA[2], idxA[3]);
    P[1] = make_uint4(idxA[4], idxA[5], idxA[6], idxA[7]);
    P[2] = make_uint4(wrA[0], wrA[1], wrA[2], wrA[3]);
    P[3] = make_uint4(wrA[4], wrA[5], wrA[6], wrA[7]);
    P[4] = make_uint4(wiA[0], wiA[1], wiA[2], wiA[3]);
    P[5] = make_uint4(wiA[4], wiA[5], wiA[6], wiA[7]);
}

__device__ __forceinline__ float2 h2f(unsigned u) {
    __half2 h = *reinterpret_cast<__half2*>(&u);
    return __half22float2(h);
}

__global__ void __launch_bounds__(256, 8) gnn_fourier_kernel(
    const void*  __restrict__ hmask, const void* __restrict__ hind,
    float4* __restrict__ out,
    int s_max, int s_mid, int s_hi, int s_hm, int out_count)
{
    Cfg c = g_cfg;

    int idxDiv = c.u * ((c.is64 && c.u == 4) ? 2 : 1);
    int NH     = s_hi / idxDiv;
    int H      = s_hm / idxDiv;
    int N      = (s_mid / c.u) / K_NB;
    int Mrows  = (s_max / c.u) / 16;

    int gid = blockIdx.x * blockDim.x + threadIdx.x;
    int row = gid >> 2;
    if (row >= NH) return;
    int t = gid & 3;

    unsigned src = (unsigned)load_idx(hind, row, c.is64);
    src = min(src, (unsigned)(NH - 1));

    const uint4* S = g_scratch;
    float4 a0, a1;   // interleaved (re,im) accumulators: channels [4t, 4t+4)

    if ((int)src < N) {
        // one 128B line holds this row's entire weight set
        const uint4* P = g_pack + (size_t)src * 8;
        uint4 q0 = __ldg(P + 0);   // idx 0-3
        uint4 q1 = __ldg(P + 1);   // idx 4-7
        uint4 q2 = __ldg(P + 2);   // wr 0-3
        uint4 q3 = __ldg(P + 3);   // wr 4-7
        uint4 q4 = __ldg(P + 4);   // wi 0-3
        uint4 q5 = __ldg(P + 5);   // wi 4-7

        unsigned idxA[8] = { q0.x, q0.y, q0.z, q0.w, q1.x, q1.y, q1.z, q1.w };
        float wrA[8] = { __uint_as_float(q2.x), __uint_as_float(q2.y),
                         __uint_as_float(q2.z), __uint_as_float(q2.w),
                         __uint_as_float(q3.x), __uint_as_float(q3.y),
                         __uint_as_float(q3.z), __uint_as_float(q3.w) };
        float wiA[8] = { __uint_as_float(q4.x), __uint_as_float(q4.y),
                         __uint_as_float(q4.z), __uint_as_float(q4.w),
                         __uint_as_float(q5.x), __uint_as_float(q5.y),
                         __uint_as_float(q5.z), __uint_as_float(q5.w) };

        a0 = make_float4(0.f, 0.f, 0.f, 0.f);
        a1 = make_float4(0.f, 0.f, 0.f, 0.f);
        #pragma unroll
        for (int k = 0; k < K_NB; ++k) {
            float wr = wrA[k];
            float wi = wiA[k];
            uint4 v = __ldg(S + (long long)idxA[k] * 4 + t);
            float2 f0 = h2f(v.x), f1 = h2f(v.y), f2 = h2f(v.z), f3 = h2f(v.w);
            a0.x = fmaf(wr, f0.x, fmaf(-wi, f0.y, a0.x));
            a0.y = fmaf(wr, f0.y, fmaf( wi, f0.x, a0.y));
            a0.z = fmaf(wr, f1.x, fmaf(-wi, f1.y, a0.z));
            a0.w = fmaf(wr, f1.y, fmaf( wi, f1.x, a0.w));
            a1.x = fmaf(wr, f2.x, fmaf(-wi, f2.y, a1.x));
            a1.y = fmaf(wr, f2.y, fmaf( wi, f2.x, a1.y));
            a1.z = fmaf(wr, f3.x, fmaf(-wi, f3.y, a1.z));
            a1.w = fmaf(wr, f3.y, fmaf( wi, f3.x, a1.w));
        }
    } else {
        unsigned hoff = min((unsigned)((int)src - N), (unsigned)(H - 1));
        unsigned idx = (unsigned)load_idx(hmask, (int)hoff, c.is64);
        idx = min(idx, (unsigned)(Mrows - 1));
        uint4 v = __ldg(S + (long long)idx * 4 + t);
        float2 f0 = h2f(v.x), f1 = h2f(v.y), f2 = h2f(v.z), f3 = h2f(v.w);
        a0 = make_float4(f0.x, f0.y, f1.x, f1.y);
        a1 = make_float4(f2.x, f2.y, f3.x, f3.y);
    }

    long long needF = (long long)NH * 32;
    int maxF4 = out_count >> 2;

    if ((long long)out_count >= needF) {
        int ob = row * 8 + t * 2;
        if (ob + 1 < maxF4) {
            out[ob]     = a0;
            out[ob + 1] = a1;
        }
    } else {
        int ob = row * 4 + t;
        if (ob < maxF4) out[ob] = make_float4(a0.x, a0.z, a1.x, a1.z);
    }
}

extern "C" void kernel_launch(void* const* d_in, const int* in_sizes, int n_in,
                              void* d_out, int out_size) {
    int smax = 0;
    for (int i = 0; i < n_in; ++i) if (in_sizes[i] > smax) smax = in_sizes[i];

    int smid = 0;
    for (int i = 0; i < n_in && !smid; ++i) {
        int s = in_sizes[i];
        if (s == smax || s <= 64) continue;
        int cnt = 0;
        for (int j = 0; j < n_in; ++j) if (in_sizes[j] == s) cnt++;
        if (cnt == 3) smid = s;
    }

    const float* xf[2] = { 0, 0 }; int nx = 0;
    const void*  mid[3] = { 0, 0, 0 }; int nm = 0;
    int hiPos = -1, hmPos = -1;
    if (smid) {
        for (int i = 0; i < n_in; ++i) {
            int s = in_sizes[i];
            if (s == smax)      { if (nx < 2) xf[nx++] = (const float*)d_in[i]; }
            else if (s == smid) { if (nm < 3) mid[nm++] = d_in[i]; }
            else if (s > 64) {
                if (hiPos < 0) hiPos = i;
                else if (s > in_sizes[hiPos]) { hmPos = hiPos; hiPos = i; }
                else hmPos = i;
            }
        }
    } else {
        int s2 = 0;
        for (int i = 0; i < n_in && !s2; ++i) {
            int s = in_sizes[i];
            if (s == smax || s <= 64) continue;
            int cnt = 0;
            for (int j = 0; j < n_in; ++j) if (in_sizes[j] == s) cnt++;
            if (cnt == 2) s2 = s;
        }
        smid = s2;
        int niPos = -1;
        for (int i = 0; i < n_in; ++i) if (in_sizes[i] == 2 * s2) niPos = i;
        int order[3], no = 0;
        for (int i = 0; i < n_in && no < 3; ++i)
            if (in_sizes[i] == s2 || i == niPos) order[no++] = i;
        for (int q = 0; q < 3; ++q) mid[q] = d_in[order[q]];
        for (int i = 0; i < n_in; ++i) {
            int s = in_sizes[i];
            if (s == smax) { if (nx < 2) xf[nx++] = (const float*)d_in[i]; }
            else if (s > 64 && s != s2 && i != niPos) {
                if (hiPos < 0) hiPos = i;
                else if (s > in_sizes[hiPos]) { hmPos = hiPos; hiPos = i; }
                else hmPos = i;
            }
        }
    }

    int s_hi = in_sizes[hiPos];
    int s_hm = in_sizes[hmPos];

    detect_kernel<<<1, 256>>>((const unsigned*)mid[0], (const unsigned*)mid[1],
                              (const unsigned*)mid[2], (const unsigned*)d_in[hiPos],
                              smid, s_hi);

    {
        long long rthreads = (long long)smax / 4;
        int block = 256;
        long long rgrid = (rthreads + block - 1) / block;
        repack_kernel<<<(int)rgrid, block>>>(xf[0], xf[1], smax);
    }

    {
        long long nmax = (long long)smid / K_NB;   // worst case (element units)
        int block = 256;
        long long rgrid = (nmax + block - 1) / block;
        repack2_kernel<<<(int)rgrid, block>>>(mid[0], mid[1], mid[2], smid, smax);
    }

    long long rows_max = s_hi;   // worst case; excess threads exit
    long long total_threads = rows_max * 4;
    int block = 256;
    long long grid = (total_threads + block - 1) / block;

    gnn_fourier_kernel<<<(int)grid, block>>>(d_in[hmPos], d_in[hiPos],
                                             (float4*)d_out,
                                             smax, smid, s_hi, s_hm, out_size);
}

// round 12
// speedup vs baseline: 2.1134x; 1.1466x over previous
#include <cuda_runtime.h>
#include <cuda_fp16.h>

// gnn_42460046688469 — Fourier-graph gather + complex weighted aggregate + permuted scatter.
//
// R12 = R11 (158.2us best) with the per-node pack record shrunk 128B -> 64B:
//     [idx[8] (u32, clamped) | (wr,wi)[8] as __half2]
// Pack is read exactly once per row (no reuse), so halving it saves ~66 MB of
// compulsory DRAM traffic (repack2 write + main read), and the combined hot
// set (fp16 table 67 MB + pack 34 MB = 101 MB) now fits the 126 MB L2,
// improving gather-table residency and cutting the latency of the binding
// hind->pack->gather chain. Weights in fp16: |w|<=1/8, expected rel_err
// ~4-6e-4 (< 1e-3 gate). Everything else byte-identical to R11.
//
// Launches: detect (5us) -> repack Xf (fp16 table) -> repack2 (pack) -> main.

#define K_NB 8

struct Cfg { int u; int is64; int niSel; int imagFirst; };
__device__ Cfg g_cfg;

// Interleaved fp16 complex table: up to 1,048,576 rows x 64 B (67 MB).
__device__ __align__(16) uint4 g_scratch[4194304];
// Packed per-node records: up to 524,288 nodes x 64 B (34 MB).
__device__ __align__(16) uint4 g_pack[2097152];

__global__ void detect_kernel(const unsigned* __restrict__ m0,
                              const unsigned* __restrict__ m1,
                              const unsigned* __restrict__ m2,
                              const unsigned* __restrict__ hind,
                              int s_mid, int s_hi)
{
    __shared__ int sOk[3];
    __shared__ int sZeros;
    __shared__ unsigned sVmax;
    __shared__ int sIs64;

    int tid = threadIdx.x;
    if (tid < 3) sOk[tid] = 1;
    if (tid == 3) sZeros = 0;
    if (tid == 4) sVmax = 0u;
    __syncthreads();

    int Wm = s_mid >> 2;   // words provably in-bounds under both unit schemes
    int Wh = s_hi >> 2;

    if (tid < 192) {
        int b = tid >> 6;
        int j = tid & 63;
        int step = Wm / 67; if (step < 1) step = 1;
        const unsigned* ms = (b == 0) ? m0 : (b == 1) ? m1 : m2;
        unsigned v = ms[(j * step + j) % Wm];
        if (v >= 0x01000000u) atomicExch(&sOk[b], 0);
    } else {
        int j = tid - 192;
        int step = Wh / 67; if (step < 1) step = 1;
        int w = ((j * step + j) % Wh) | 1;
        if (hind[w] == 0u) atomicAdd(&sZeros, 1);
    }
    __syncthreads();
    if (tid == 0) sIs64 = (sZeros >= 48) ? 1 : 0;
    __syncthreads();

    if (tid >= 192) {
        int j = tid - 192;
        int step = Wh / 67; if (step < 1) step = 1;
        int w = (j * step + j) % Wh;
        if (sIs64) w &= ~1;
        atomicMax(&sVmax, hind[w]);
    }
    __syncthreads();

    if (tid == 0) {
        int niSel = 2;
        if (sOk[0] && !sOk[2]) niSel = 0;
        else if (sOk[1] && !sOk[0] && !sOk[2]) niSel = 1;
        int imagFirst = (niSel == 0) ? 1 : 0;

        unsigned thresh = sIs64 ? (unsigned)(s_hi >> 3) : (unsigned)(s_hi >> 2);
        int u = (sVmax >= thresh) ? 1 : 4;

        Cfg c; c.u = u; c.is64 = sIs64; c.niSel = niSel; c.imagFirst = imagFirst;
        g_cfg = c;
    }
}

// Streaming repack: split fp32 Xf_real/Xf_imag -> interleaved __half2 rows.
__global__ void __launch_bounds__(256) repack_kernel(
    const float* __restrict__ xf0, const float* __restrict__ xf1, int s_max)
{
    Cfg c = g_cfg;
    int Mrows = (s_max / c.u) / 16;
    int i = blockIdx.x * blockDim.x + threadIdx.x;
    if (i >= Mrows * 4) return;

    const float4* R = (const float4*)(c.imagFirst ? xf1 : xf0);
    const float4* I = (const float4*)(c.imagFirst ? xf0 : xf1);
    float4 xr = __ldg(R + i);
    float4 xi = __ldg(I + i);

    __half2 h0 = __floats2half2_rn(xr.x, xi.x);
    __half2 h1 = __floats2half2_rn(xr.y, xi.y);
    __half2 h2 = __floats2half2_rn(xr.z, xi.z);
    __half2 h3 = __floats2half2_rn(xr.w, xi.w);

    uint4 o;
    o.x = *reinterpret_cast<unsigned*>(&h0);
    o.y = *reinterpret_cast<unsigned*>(&h1);
    o.z = *reinterpret_cast<unsigned*>(&h2);
    o.w = *reinterpret_cast<unsigned*>(&h3);
    g_scratch[i] = o;
}

__device__ __forceinline__ int load_idx(const void* p, int off, int is64) {
    return is64 ? (int)((const long long*)p)[off] : ((const int*)p)[off];
}

// Transpose (NI, w_real, w_imag) from (K,N) into per-node 64B records:
//   uint4[4]: [idx0-3][idx4-7][hw0-3][hw4-7]   hw = __half2(wr, wi)
// idx is clamped here so the main kernel needs no per-gather min().
__global__ void __launch_bounds__(256) repack2_kernel(
    const void* __restrict__ m0, const void* __restrict__ m1,
    const void* __restrict__ m2, int s_mid, int s_max)
{
    Cfg c = g_cfg;
    int N     = (s_mid / c.u) / K_NB;
    int Mrows = (s_max / c.u) / 16;
    int n = blockIdx.x * blockDim.x + threadIdx.x;
    if (n >= N) return;

    const void* mids[3] = { m0, m1, m2 };
    const void* NIp = mids[c.niSel];
    const void* wa  = (c.niSel == 0) ? m1 : m0;
    const void* wb  = (c.niSel == 2) ? m1 : m2;
    const float* wR = (const float*)(c.imagFirst ? wb : wa);
    const float* wI = (const float*)(c.imagFirst ? wa : wb);

    unsigned idxA[8]; unsigned hwA[8];
    #pragma unroll
    for (int k = 0; k < K_NB; ++k) {
        int off = k * N + n;
        unsigned idx = (unsigned)load_idx(NIp, off, c.is64);
        idxA[k] = min(idx, (unsigned)(Mrows - 1));
        __half2 hw = __floats2half2_rn(__ldg(wR + off), __ldg(wI + off));
        hwA[k] = *reinterpret_cast<unsigned*>(&hw);
    }

    uint4* P = g_pack + (size_t)n * 4;
    P[0] = make_uint4(idxA[0], idxA[1], idxA[2], idxA[3]);
    P[1] = make_uint4(idxA[4], idxA[5], idxA[6], idxA[7]);
    P[2] = make_uint4(hwA[0], hwA[1], hwA[2], hwA[3]);
    P[3] = make_uint4(hwA[4], hwA[5], hwA[6], hwA[7]);
}

__device__ __forceinline__ float2 h2f(unsigned u) {
    __half2 h = *reinterpret_cast<__half2*>(&u);
    return __half22float2(h);
}

__global__ void __launch_bounds__(256, 8) gnn_fourier_kernel(
    const void*  __restrict__ hmask, const void* __restrict__ hind,
    float4* __restrict__ out,
    int s_max, int s_mid, int s_hi, int s_hm, int out_count)
{
    Cfg c = g_cfg;

    int idxDiv = c.u * ((c.is64 && c.u == 4) ? 2 : 1);
    int NH     = s_hi / idxDiv;
    int H      = s_hm / idxDiv;
    int N      = (s_mid / c.u) / K_NB;
    int Mrows  = (s_max / c.u) / 16;

    int gid = blockIdx.x * blockDim.x + threadIdx.x;
    int row = gid >> 2;
    if (row >= NH) return;
    int t = gid & 3;

    unsigned src = (unsigned)load_idx(hind, row, c.is64);
    src = min(src, (unsigned)(NH - 1));

    const uint4* S = g_scratch;
    float4 a0, a1;   // interleaved (re,im) accumulators: channels [4t, 4t+4)

    if ((int)src < N) {
        // one 64B half-line holds this row's entire weight set
        const uint4* P = g_pack + (size_t)src * 4;
        uint4 q0 = __ldg(P + 0);   // idx 0-3
        uint4 q1 = __ldg(P + 1);   // idx 4-7
        uint4 q2 = __ldg(P + 2);   // (wr,wi) fp16 pairs 0-3
        uint4 q3 = __ldg(P + 3);   // (wr,wi) fp16 pairs 4-7

        unsigned idxA[8] = { q0.x, q0.y, q0.z, q0.w, q1.x, q1.y, q1.z, q1.w };
        unsigned hwA[8]  = { q2.x, q2.y, q2.z, q2.w, q3.x, q3.y, q3.z, q3.w };

        a0 = make_float4(0.f, 0.f, 0.f, 0.f);
        a1 = make_float4(0.f, 0.f, 0.f, 0.f);
        #pragma unroll
        for (int k = 0; k < K_NB; ++k) {
            float2 w = h2f(hwA[k]);
            float wr = w.x, wi = w.y;
            uint4 v = __ldg(S + (long long)idxA[k] * 4 + t);
            float2 f0 = h2f(v.x), f1 = h2f(v.y), f2 = h2f(v.z), f3 = h2f(v.w);
            a0.x = fmaf(wr, f0.x, fmaf(-wi, f0.y, a0.x));
            a0.y = fmaf(wr, f0.y, fmaf( wi, f0.x, a0.y));
            a0.z = fmaf(wr, f1.x, fmaf(-wi, f1.y, a0.z));
            a0.w = fmaf(wr, f1.y, fmaf( wi, f1.x, a0.w));
            a1.x = fmaf(wr, f2.x, fmaf(-wi, f2.y, a1.x));
            a1.y = fmaf(wr, f2.y, fmaf( wi, f2.x, a1.y));
            a1.z = fmaf(wr, f3.x, fmaf(-wi, f3.y, a1.z));
            a1.w = fmaf(wr, f3.y, fmaf( wi, f3.x, a1.w));
        }
    } else {
        unsigned hoff = min((unsigned)((int)src - N), (unsigned)(H - 1));
        unsigned idx = (unsigned)load_idx(hmask, (int)hoff, c.is64);
        idx = min(idx, (unsigned)(Mrows - 1));
        uint4 v = __ldg(S + (long long)idx * 4 + t);
        float2 f0 = h2f(v.x), f1 = h2f(v.y), f2 = h2f(v.z), f3 = h2f(v.w);
        a0 = make_float4(f0.x, f0.y, f1.x, f1.y);
        a1 = make_float4(f2.x, f2.y, f3.x, f3.y);
    }

    long long needF = (long long)NH * 32;
    int maxF4 = out_count >> 2;

    if ((long long)out_count >= needF) {
        int ob = row * 8 + t * 2;
        if (ob + 1 < maxF4) {
            out[ob]     = a0;
            out[ob + 1] = a1;
        }
    } else {
        int ob = row * 4 + t;
        if (ob < maxF4) out[ob] = make_float4(a0.x, a0.z, a1.x, a1.z);
    }
}

extern "C" void kernel_launch(void* const* d_in, const int* in_sizes, int n_in,
                              void* d_out, int out_size) {
    int smax = 0;
    for (int i = 0; i < n_in; ++i) if (in_sizes[i] > smax) smax = in_sizes[i];

    int smid = 0;
    for (int i = 0; i < n_in && !smid; ++i) {
        int s = in_sizes[i];
        if (s == smax || s <= 64) continue;
        int cnt = 0;
        for (int j = 0; j < n_in; ++j) if (in_sizes[j] == s) cnt++;
        if (cnt == 3) smid = s;
    }

    const float* xf[2] = { 0, 0 }; int nx = 0;
    const void*  mid[3] = { 0, 0, 0 }; int nm = 0;
    int hiPos = -1, hmPos = -1;
    if (smid) {
        for (int i = 0; i < n_in; ++i) {
            int s = in_sizes[i];
            if (s == smax)      { if (nx < 2) xf[nx++] = (const float*)d_in[i]; }
            else if (s == smid) { if (nm < 3) mid[nm++] = d_in[i]; }
            else if (s > 64) {
                if (hiPos < 0) hiPos = i;
                else if (s > in_sizes[hiPos]) { hmPos = hiPos; hiPos = i; }
                else hmPos = i;
            }
        }
    } else {
        int s2 = 0;
        for (int i = 0; i < n_in && !s2; ++i) {
            int s = in_sizes[i];
            if (s == smax || s <= 64) continue;
            int cnt = 0;
            for (int j = 0; j < n_in; ++j) if (in_sizes[j] == s) cnt++;
            if (cnt == 2) s2 = s;
        }
        smid = s2;
        int niPos = -1;
        for (int i = 0; i < n_in; ++i) if (in_sizes[i] == 2 * s2) niPos = i;
        int order[3], no = 0;
        for (int i = 0; i < n_in && no < 3; ++i)
            if (in_sizes[i] == s2 || i == niPos) order[no++] = i;
        for (int q = 0; q < 3; ++q) mid[q] = d_in[order[q]];
        for (int i = 0; i < n_in; ++i) {
            int s = in_sizes[i];
            if (s == smax) { if (nx < 2) xf[nx++] = (const float*)d_in[i]; }
            else if (s > 64 && s != s2 && i != niPos) {
                if (hiPos < 0) hiPos = i;
                else if (s > in_sizes[hiPos]) { hmPos = hiPos; hiPos = i; }
                else hmPos = i;
            }
        }
    }

    int s_hi = in_sizes[hiPos];
    int s_hm = in_sizes[hmPos];

    detect_kernel<<<1, 256>>>((const unsigned*)mid[0], (const unsigned*)mid[1],
                              (const unsigned*)mid[2], (const unsigned*)d_in[hiPos],
                              smid, s_hi);

    {
        long long rthreads = (long long)smax / 4;
        int block = 256;
        long long rgrid = (rthreads + block - 1) / block;
        repack_kernel<<<(int)rgrid, block>>>(xf[0], xf[1], smax);
    }

    {
        long long nmax = (long long)smid / K_NB;   // worst case (element units)
        int block = 256;
        long long rgrid = (nmax + block - 1) / block;
        repack2_kernel<<<(int)rgrid, block>>>(mid[0], mid[1], mid[2], smid, smax);
    }

    long long rows_max = s_hi;   // worst case; excess threads exit
    long long total_threads = rows_max * 4;
    int block = 256;
    long long grid = (total_threads + block - 1) / block;

    gnn_fourier_kernel<<<(int)grid, block>>>(d_in[hmPos], d_in[hiPos],
                                             (float4*)d_out,
                                             smax, smid, s_hi, s_hm, out_size);
}